// round 2
// baseline (speedup 1.0000x reference)
#include <cuda_runtime.h>
#include <math.h>

#define BB   4
#define CIN  128
#define COUT 128
#define HH   96
#define WW   96
#define KK   3
#define K2   9

#define OUT_MAIN_ELEMS (BB*COUT*HH*WW)   // 4718592
#define OFF_ELEMS      (BB*18*HH*WW)     // 663552

// ---- device scratch (no allocations allowed) ----
__device__ float g_xt[BB*HH*WW*CIN];      // x in NHWC, ~18.9 MB
__device__ float g_mask[BB*K2*HH*WW];     // sigmoid(om[18:27])*2
__device__ float g_wt[K2*CIN*COUT];       // main weight, [tap][c][oc]
__device__ float g_wofft[K2*27*CIN];      // offset weight, [tap][oc27][c]

// ============================================================
// 1) NCHW -> NHWC transpose of x (tiled via smem)
//    grid (W/32=3, C/32=4, B*H), block (32,8)
// ============================================================
__global__ void transpose_nchw_nhwc(const float* __restrict__ x) {
    __shared__ float t[32][33];
    int w0 = blockIdx.x * 32;
    int c0 = blockIdx.y * 32;
    int bh = blockIdx.z;
    int b = bh / HH;
    int h = bh % HH;
    const float* xb = x + (size_t)b * CIN * HH * WW;
#pragma unroll
    for (int i = 0; i < 32; i += 8) {
        int c = c0 + threadIdx.y + i;
        t[threadIdx.y + i][threadIdx.x] = xb[((size_t)c * HH + h) * WW + w0 + threadIdx.x];
    }
    __syncthreads();
    float* xt = g_xt + ((size_t)b * HH + h) * WW * CIN;
#pragma unroll
    for (int i = 0; i < 32; i += 8) {
        int w = w0 + threadIdx.y + i;
        xt[(size_t)w * CIN + c0 + threadIdx.x] = t[threadIdx.x][threadIdx.y + i];
    }
}

// ============================================================
// 2) Weight transposes (tiny)
// ============================================================
__global__ void transpose_weights(const float* __restrict__ weight,
                                  const float* __restrict__ w_off) {
    int idx = blockIdx.x * 256 + threadIdx.x;
    if (idx < K2 * CIN * COUT) {
        int tap = idx / (CIN * COUT);
        int r   = idx % (CIN * COUT);
        int c   = r / COUT;
        int oc  = r % COUT;
        g_wt[idx] = weight[((size_t)oc * CIN + c) * K2 + tap];
    }
    if (idx < K2 * 27 * CIN) {
        int tap = idx / (27 * CIN);
        int r   = idx % (27 * CIN);
        int oc  = r / CIN;
        int c   = r % CIN;
        g_wofft[idx] = w_off[((size_t)oc * CIN + c) * K2 + tap];
    }
}

// ============================================================
// 3) Offset/mask conv: om[b,27,h,w] = conv3x3(x, w_offmask)
//    Writes om[:, :18] to the offset output, mask to g_mask.
//    grid (6,6,B), 256 threads = 16x16 pixel tile, 27 acc regs.
// ============================================================
__global__ __launch_bounds__(256) void offset_conv(float* __restrict__ out_off) {
    __shared__ float ws[27 * CIN];   // 13.8 KB, per-tap slice
    int b   = blockIdx.z;
    int ho0 = blockIdx.y * 16;
    int wo0 = blockIdx.x * 16;
    int ty = threadIdx.x >> 4;
    int tx = threadIdx.x & 15;
    int ho = ho0 + ty;
    int wo = wo0 + tx;

    float acc[27];
#pragma unroll
    for (int i = 0; i < 27; i++) acc[i] = 0.f;

    const float* xt = g_xt + (size_t)b * HH * WW * CIN;

    for (int tap = 0; tap < 9; tap++) {
        __syncthreads();
        {
            const float4* src = (const float4*)(g_wofft + tap * 27 * CIN);
            float4* dst = (float4*)ws;
            for (int i = threadIdx.x; i < 27 * CIN / 4; i += 256) dst[i] = src[i];
        }
        __syncthreads();

        int ki = tap / 3, kj = tap % 3;
        int y = ho + ki - 1;
        int x = wo + kj - 1;
        bool ok = (y >= 0) && (y < HH) && (x >= 0) && (x < WW);
        if (ok) {
            const float4* xp = (const float4*)(xt + ((size_t)y * WW + x) * CIN);
            const float4* ws4 = (const float4*)ws;
#pragma unroll 2
            for (int c4 = 0; c4 < CIN / 4; c4++) {
                float4 xv = xp[c4];
#pragma unroll
                for (int oc = 0; oc < 27; oc++) {
                    float4 wv = ws4[oc * (CIN / 4) + c4];
                    acc[oc] += xv.x * wv.x + xv.y * wv.y + xv.z * wv.z + xv.w * wv.w;
                }
            }
        }
    }

    // epilogue: offsets (raw) + mask (sigmoid*2)
#pragma unroll
    for (int oc = 0; oc < 18; oc++)
        out_off[(((size_t)b * 18 + oc) * HH + ho) * WW + wo] = acc[oc];
#pragma unroll
    for (int k = 0; k < 9; k++) {
        float v = acc[18 + k];
        g_mask[(((size_t)b * 9 + k) * HH + ho) * WW + wo] = 2.0f / (1.0f + expf(-v));
    }
}

// ============================================================
// 4) Deformable conv as per-tap (gather -> smem) + tiled GEMM
//    Tile: 64 px (2 ho x 32 wo) x 128 oc, K = 9 taps x 128 c.
//    256 threads; GEMM thread tile 8 oc x 4 px.
//    Dyn smem: ws[128c][128oc] (64KB) + vs[128c][64px] (32KB)
// ============================================================
__global__ __launch_bounds__(256) void deform_gemm(
    const float* __restrict__ bias,
    const float* __restrict__ off,    // [B,18,H,W] (o1 | o2)
    float* __restrict__ out)          // [B,128,H,W]
{
    extern __shared__ float smem[];
    float* ws = smem;                 // [c][oc]
    float* vs = smem + CIN * COUT;    // [c][px]

    int b   = blockIdx.z;
    int ho0 = blockIdx.y * 2;
    int wo0 = blockIdx.x * 32;
    int tid = threadIdx.x;

    // gather role: 4 threads per pixel, 32 channels each
    int gpx = tid >> 2;                 // 0..63
    int gcq = tid & 3;                  // 0..3
    int g_ho = ho0 + (gpx >> 5);
    int g_wo = wo0 + (gpx & 31);

    // gemm role
    int ty  = tid >> 4;                 // 0..15
    int tx  = tid & 15;                 // 0..15
    int oc0 = ty * 8;

    float acc[8][4];
#pragma unroll
    for (int i = 0; i < 8; i++)
#pragma unroll
        for (int j = 0; j < 4; j++) acc[i][j] = 0.f;

    const float* xt = g_xt + (size_t)b * HH * WW * CIN;

    for (int tap = 0; tap < 9; tap++) {
        __syncthreads();
        // ---- stage weights [c][oc] for this tap ----
        {
            const float4* wsrc = (const float4*)(g_wt + tap * CIN * COUT);
            float4* wdst = (float4*)ws;
#pragma unroll
            for (int i = 0; i < 16; i++) wdst[tid + 256 * i] = wsrc[tid + 256 * i];
        }

        // ---- bilinear gather + modulate into vs[c][px] ----
        int ki = tap / 3, kj = tap % 3;
        float o1 = off[(((size_t)b * 18 + tap) * HH + g_ho) * WW + g_wo];
        float o2 = off[(((size_t)b * 18 + 9 + tap) * HH + g_ho) * WW + g_wo];
        float m  = g_mask[(((size_t)b * 9 + tap) * HH + g_ho) * WW + g_wo];

        float py  = (float)(g_ho - 1 + ki) + o1;
        float pxx = (float)(g_wo - 1 + kj) + o2;
        float y0f = floorf(py), x0f = floorf(pxx);
        float ly = py - y0f, lx = pxx - x0f;
        float hy = 1.f - ly, hx = 1.f - lx;
        int y0 = (int)y0f, x0 = (int)x0f;
        int y1 = y0 + 1, x1 = x0 + 1;
        bool vy0 = (y0 >= 0) && (y0 < HH), vy1 = (y1 >= 0) && (y1 < HH);
        bool vx0 = (x0 >= 0) && (x0 < WW), vx1 = (x1 >= 0) && (x1 < WW);
        float w00 = (vy0 && vx0) ? hy * hx * m : 0.f;
        float w01 = (vy0 && vx1) ? hy * lx * m : 0.f;
        float w10 = (vy1 && vx0) ? ly * hx * m : 0.f;
        float w11 = (vy1 && vx1) ? ly * lx * m : 0.f;
        int y0c = min(max(y0, 0), HH - 1), y1c = min(max(y1, 0), HH - 1);
        int x0c = min(max(x0, 0), WW - 1), x1c = min(max(x1, 0), WW - 1);
        const float4* p00 = (const float4*)(xt + ((size_t)y0c * WW + x0c) * CIN);
        const float4* p01 = (const float4*)(xt + ((size_t)y0c * WW + x1c) * CIN);
        const float4* p10 = (const float4*)(xt + ((size_t)y1c * WW + x0c) * CIN);
        const float4* p11 = (const float4*)(xt + ((size_t)y1c * WW + x1c) * CIN);

#pragma unroll
        for (int i = 0; i < 8; i++) {
            int c4 = gcq * 8 + i;
            float4 v00 = p00[c4], v01 = p01[c4], v10 = p10[c4], v11 = p11[c4];
            float r0 = w00 * v00.x + w01 * v01.x + w10 * v10.x + w11 * v11.x;
            float r1 = w00 * v00.y + w01 * v01.y + w10 * v10.y + w11 * v11.y;
            float r2 = w00 * v00.z + w01 * v01.z + w10 * v10.z + w11 * v11.z;
            float r3 = w00 * v00.w + w01 * v01.w + w10 * v10.w + w11 * v11.w;
            int c = c4 * 4;
            vs[(c + 0) * 64 + gpx] = r0;
            vs[(c + 1) * 64 + gpx] = r1;
            vs[(c + 2) * 64 + gpx] = r2;
            vs[(c + 3) * 64 + gpx] = r3;
        }
        __syncthreads();

        // ---- GEMM: acc[oc][px] += ws[c][oc] * vs[c][px] ----
#pragma unroll 4
        for (int c = 0; c < CIN; c++) {
            const float4* wrow = (const float4*)(ws + c * COUT + oc0);
            float4 wv0 = wrow[0];
            float4 wv1 = wrow[1];
            float4 vv  = *((const float4*)(vs + c * 64 + tx * 4));
            float wr[8] = {wv0.x, wv0.y, wv0.z, wv0.w, wv1.x, wv1.y, wv1.z, wv1.w};
            float vr[4] = {vv.x, vv.y, vv.z, vv.w};
#pragma unroll
            for (int i = 0; i < 8; i++)
#pragma unroll
                for (int j = 0; j < 4; j++)
                    acc[i][j] += wr[i] * vr[j];
        }
    }

    // ---- epilogue: + bias, write NCHW ----
    int e_ho = ho0 + (tx >> 3);
    int e_wo = wo0 + ((tx & 7) * 4);
#pragma unroll
    for (int i = 0; i < 8; i++) {
        float bv = bias[oc0 + i];
        float4 r = make_float4(acc[i][0] + bv, acc[i][1] + bv,
                               acc[i][2] + bv, acc[i][3] + bv);
        *((float4*)(out + (((size_t)b * COUT + oc0 + i) * HH + e_ho) * WW + e_wo)) = r;
    }
}

// ============================================================
// launch
// ============================================================
extern "C" void kernel_launch(void* const* d_in, const int* in_sizes, int n_in,
                              void* d_out, int out_size) {
    (void)in_sizes; (void)n_in; (void)out_size;
    const float* x      = (const float*)d_in[0];
    const float* weight = (const float*)d_in[1];
    const float* bias   = (const float*)d_in[2];
    const float* w_off  = (const float*)d_in[3];

    float* out = (float*)d_out;
    float* off = out + OUT_MAIN_ELEMS;   // second output: offsets [B,18,H,W]

    cudaFuncSetAttribute(deform_gemm, cudaFuncAttributeMaxDynamicSharedMemorySize,
                         (CIN * COUT + CIN * 64) * (int)sizeof(float));

    transpose_nchw_nhwc<<<dim3(WW / 32, CIN / 32, BB * HH), dim3(32, 8)>>>(x);
    transpose_weights<<<(K2 * CIN * COUT + 255) / 256, 256>>>(weight, w_off);
    offset_conv<<<dim3(WW / 16, HH / 16, BB), 256>>>(off);
    deform_gemm<<<dim3(WW / 32, HH / 2, BB), 256,
                  (CIN * COUT + CIN * 64) * (int)sizeof(float)>>>(bias, off, out);
}

// round 5
// speedup vs baseline: 1.8814x; 1.8814x over previous
#include <cuda_runtime.h>
#include <math.h>
#include <stdint.h>

#define BB   4
#define CIN  128
#define COUT 128
#define HH   96
#define WW   96
#define K2   9

#define OUT_MAIN_ELEMS (BB*COUT*HH*WW)   // 4718592
#define PLANE (HH*WW)                    // 9216

// ---- device scratch (no allocations allowed) ----
__device__ float g_xt[BB*HH*WW*CIN];      // x in NHWC
__device__ float g_mask[BB*K2*HH*WW];     // sigmoid(om[18:27])*2
__device__ float g_wt2[K2*4*128*32];      // tf32-rounded weights: [tap*4+cq][oc][c32]
__device__ float g_wofft[K2*27*CIN];      // offset weight, [tap][oc27][c]

__device__ __forceinline__ uint32_t f2tf32(float x) {
    uint32_t u;
    asm("cvt.rna.tf32.f32 %0, %1;" : "=r"(u) : "f"(x));
    return u;
}

__device__ __forceinline__ void mma_tf32(float d[4], const uint32_t a[4], const uint32_t b[2]) {
    asm volatile(
        "mma.sync.aligned.m16n8k8.row.col.f32.tf32.tf32.f32 "
        "{%0,%1,%2,%3}, {%4,%5,%6,%7}, {%8,%9}, {%0,%1,%2,%3};"
        : "+f"(d[0]), "+f"(d[1]), "+f"(d[2]), "+f"(d[3])
        : "r"(a[0]), "r"(a[1]), "r"(a[2]), "r"(a[3]), "r"(b[0]), "r"(b[1]));
}

// ============================================================
// 1) NCHW -> NHWC transpose of x
// ============================================================
__global__ void transpose_nchw_nhwc(const float* __restrict__ x) {
    __shared__ float t[32][33];
    int w0 = blockIdx.x * 32;
    int c0 = blockIdx.y * 32;
    int bh = blockIdx.z;
    int b = bh / HH;
    int h = bh % HH;
    const float* xb = x + (size_t)b * CIN * HH * WW;
#pragma unroll
    for (int i = 0; i < 32; i += 8) {
        int c = c0 + threadIdx.y + i;
        t[threadIdx.y + i][threadIdx.x] = xb[((size_t)c * HH + h) * WW + w0 + threadIdx.x];
    }
    __syncthreads();
    float* xt = g_xt + ((size_t)b * HH + h) * WW * CIN;
#pragma unroll
    for (int i = 0; i < 32; i += 8) {
        int w = w0 + threadIdx.y + i;
        xt[(size_t)w * CIN + c0 + threadIdx.x] = t[threadIdx.x][threadIdx.y + i];
    }
}

// ============================================================
// 2) Weight prep: main weight -> [tap*4+cq][oc][c32], tf32-rounded
// ============================================================
__global__ void transpose_weights(const float* __restrict__ weight,
                                  const float* __restrict__ w_off) {
    int idx = blockIdx.x * 256 + threadIdx.x;
    if (idx < K2 * CIN * COUT) {
        int tap = idx / (CIN * COUT);
        int r   = idx % (CIN * COUT);
        int c   = r >> 7;      // 0..127
        int oc  = r & 127;
        int blk = tap * 4 + (c >> 5);
        uint32_t tv = f2tf32(weight[((size_t)oc * CIN + c) * K2 + tap]);
        g_wt2[(size_t)blk * 4096 + oc * 32 + (c & 31)] = __uint_as_float(tv);
    }
    if (idx < K2 * 27 * CIN) {
        int tap = idx / (27 * CIN);
        int r   = idx % (27 * CIN);
        int oc  = r / CIN;
        int c   = r % CIN;
        g_wofft[idx] = w_off[((size_t)oc * CIN + c) * K2 + tap];
    }
}

// ============================================================
// 3) Offset/mask conv (unchanged from passing R2)
// ============================================================
__global__ __launch_bounds__(256) void offset_conv(float* __restrict__ out_off) {
    __shared__ float ws[27 * CIN];
    int b   = blockIdx.z;
    int ho0 = blockIdx.y * 16;
    int wo0 = blockIdx.x * 16;
    int ty = threadIdx.x >> 4;
    int tx = threadIdx.x & 15;
    int ho = ho0 + ty;
    int wo = wo0 + tx;

    float acc[27];
#pragma unroll
    for (int i = 0; i < 27; i++) acc[i] = 0.f;

    const float* xt = g_xt + (size_t)b * HH * WW * CIN;

    for (int tap = 0; tap < 9; tap++) {
        __syncthreads();
        {
            const float4* src = (const float4*)(g_wofft + tap * 27 * CIN);
            float4* dst = (float4*)ws;
            for (int i = threadIdx.x; i < 27 * CIN / 4; i += 256) dst[i] = src[i];
        }
        __syncthreads();

        int ki = tap / 3, kj = tap % 3;
        int y = ho + ki - 1;
        int x = wo + kj - 1;
        bool ok = (y >= 0) && (y < HH) && (x >= 0) && (x < WW);
        if (ok) {
            const float4* xp = (const float4*)(xt + ((size_t)y * WW + x) * CIN);
            const float4* ws4 = (const float4*)ws;
#pragma unroll 2
            for (int c4 = 0; c4 < CIN / 4; c4++) {
                float4 xv = xp[c4];
#pragma unroll
                for (int oc = 0; oc < 27; oc++) {
                    float4 wv = ws4[oc * (CIN / 4) + c4];
                    acc[oc] += xv.x * wv.x + xv.y * wv.y + xv.z * wv.z + xv.w * wv.w;
                }
            }
        }
    }

#pragma unroll
    for (int oc = 0; oc < 18; oc++)
        out_off[(((size_t)b * 18 + oc) * HH + ho) * WW + wo] = acc[oc];
#pragma unroll
    for (int k = 0; k < 9; k++) {
        float v = acc[18 + k];
        g_mask[(((size_t)b * 9 + k) * HH + ho) * WW + wo] = 2.0f / (1.0f + expf(-v));
    }
}

// ============================================================
// 4) Deformable conv: gather -> smem -> mma.sync tf32
//    CTA tile: M=128 px (4 ho x 32 wo) x N=128 oc; K = 36 chunks of 32 c.
//    8 warps; warp tile 32 px x 64 oc (2 m-tiles x 8 n-tiles of m16n8k8).
//    smem: As[128][36], Bs[128][36] (stride-36 padding: conflict-free frags)
// ============================================================
__global__ __launch_bounds__(256)
void deform_mma(const float* __restrict__ bias,
                const float* __restrict__ off,
                float* __restrict__ out) {
    __shared__ uint32_t As[128 * 36];
    __shared__ uint32_t Bs[128 * 36];

    int tid = threadIdx.x;
    int wid = tid >> 5, lane = tid & 31;
    int g = lane >> 2, t = lane & 3;       // mma group / thread-in-group
    int b   = blockIdx.z;
    int ho0 = blockIdx.y * 4;
    int wo0 = blockIdx.x * 32;

    int wpx0 = (wid & 3) * 32;             // warp px base (one ho row)
    int woc0 = (wid >> 2) * 64;            // warp oc base

    float acc[2][8][4];
#pragma unroll
    for (int mt = 0; mt < 2; mt++)
#pragma unroll
        for (int nt = 0; nt < 8; nt++)
#pragma unroll
            for (int r = 0; r < 4; r++) acc[mt][nt][r] = 0.f;

    // gather role: 2 threads per pixel, 16 channels each
    int p = tid >> 1, half = tid & 1;
    int g_ho = ho0 + (p >> 5);
    int g_wo = wo0 + (p & 31);
    const float* xt = g_xt + (size_t)b * HH * WW * CIN;

    float w00 = 0.f, w01 = 0.f, w10 = 0.f, w11 = 0.f;
    const float4 *p00 = nullptr, *p01 = nullptr, *p10 = nullptr, *p11 = nullptr;

    for (int chunk = 0; chunk < 36; ++chunk) {
        int tap = chunk >> 2, cq = chunk & 3;
        __syncthreads();   // previous chunk's mma done before overwriting smem

        // ---- stage weights [128 oc][32 c] -> Bs stride 36 ----
        {
            const float4* wsrc = (const float4*)(g_wt2 + (size_t)(tap * 4 + cq) * 4096);
#pragma unroll
            for (int j = 0; j < 4; j++) {
                int idx4 = tid + j * 256;
                int oc = idx4 >> 3, c4 = (idx4 & 7) * 4;
                float4 v = wsrc[idx4];
                *(float4*)&Bs[oc * 36 + c4] = v;
            }
        }

        // ---- bilinear params (once per tap) ----
        if (cq == 0) {
            float o1 = off[(((size_t)b * 18 + tap) * HH + g_ho) * WW + g_wo];
            float o2 = off[(((size_t)b * 18 + 9 + tap) * HH + g_ho) * WW + g_wo];
            float m  = g_mask[(((size_t)b * 9 + tap) * HH + g_ho) * WW + g_wo];
            int ki = tap / 3, kj = tap % 3;
            float py  = (float)(g_ho - 1 + ki) + o1;
            float pxx = (float)(g_wo - 1 + kj) + o2;
            float y0f = floorf(py), x0f = floorf(pxx);
            float ly = py - y0f, lx = pxx - x0f;
            float hy = 1.f - ly, hx = 1.f - lx;
            int y0 = (int)y0f, x0 = (int)x0f;
            int y1 = y0 + 1, x1 = x0 + 1;
            bool vy0 = (y0 >= 0) && (y0 < HH), vy1 = (y1 >= 0) && (y1 < HH);
            bool vx0 = (x0 >= 0) && (x0 < WW), vx1 = (x1 >= 0) && (x1 < WW);
            w00 = (vy0 && vx0) ? hy * hx * m : 0.f;
            w01 = (vy0 && vx1) ? hy * lx * m : 0.f;
            w10 = (vy1 && vx0) ? ly * hx * m : 0.f;
            w11 = (vy1 && vx1) ? ly * lx * m : 0.f;
            int y0c = min(max(y0, 0), HH - 1), y1c = min(max(y1, 0), HH - 1);
            int x0c = min(max(x0, 0), WW - 1), x1c = min(max(x1, 0), WW - 1);
            p00 = (const float4*)(xt + ((size_t)y0c * WW + x0c) * CIN);
            p01 = (const float4*)(xt + ((size_t)y0c * WW + x1c) * CIN);
            p10 = (const float4*)(xt + ((size_t)y1c * WW + x0c) * CIN);
            p11 = (const float4*)(xt + ((size_t)y1c * WW + x1c) * CIN);
        }

        // ---- gather + modulate 16 channels -> As[p][.] (tf32-rounded) ----
#pragma unroll
        for (int i = 0; i < 4; i++) {
            int c4 = cq * 8 + half * 4 + i;
            float4 a = p00[c4], bb = p01[c4], c = p10[c4], d = p11[c4];
            uint32_t* dst = &As[p * 36 + half * 16 + i * 4];
            dst[0] = f2tf32(w00 * a.x + w01 * bb.x + w10 * c.x + w11 * d.x);
            dst[1] = f2tf32(w00 * a.y + w01 * bb.y + w10 * c.y + w11 * d.y);
            dst[2] = f2tf32(w00 * a.z + w01 * bb.z + w10 * c.z + w11 * d.z);
            dst[3] = f2tf32(w00 * a.w + w01 * bb.w + w10 * c.w + w11 * d.w);
        }
        __syncthreads();

        // ---- mma: 4 k-steps x (2 mt x 8 nt) ----
#pragma unroll
        for (int ks = 0; ks < 4; ks++) {
            int c0 = ks * 8 + t;
            uint32_t afrag[2][4];
#pragma unroll
            for (int mt = 0; mt < 2; mt++) {
                int row = wpx0 + mt * 16 + g;
                afrag[mt][0] = As[row * 36 + c0];
                afrag[mt][1] = As[(row + 8) * 36 + c0];
                afrag[mt][2] = As[row * 36 + c0 + 4];
                afrag[mt][3] = As[(row + 8) * 36 + c0 + 4];
            }
            uint32_t bfrag[8][2];
#pragma unroll
            for (int nt = 0; nt < 8; nt++) {
                int oc = woc0 + nt * 8 + g;
                bfrag[nt][0] = Bs[oc * 36 + c0];
                bfrag[nt][1] = Bs[oc * 36 + c0 + 4];
            }
#pragma unroll
            for (int mt = 0; mt < 2; mt++)
#pragma unroll
                for (int nt = 0; nt < 8; nt++)
                    mma_tf32(acc[mt][nt], afrag[mt], bfrag[nt]);
        }
    }

    // ---- epilogue: acc -> out (NCHW) + bias ----
    int e_ho = ho0 + (wid & 3);
    float* ob = out + ((size_t)b * COUT) * PLANE + (size_t)e_ho * WW + wo0;
#pragma unroll
    for (int nt = 0; nt < 8; nt++) {
        int oc0 = woc0 + nt * 8 + 2 * t;
        float b0 = __ldg(&bias[oc0]);
        float b1 = __ldg(&bias[oc0 + 1]);
#pragma unroll
        for (int mt = 0; mt < 2; mt++) {
            int wo_a = mt * 16 + g;
            float* r0 = ob + (size_t)oc0 * PLANE + wo_a;
            float* r1 = ob + (size_t)(oc0 + 1) * PLANE + wo_a;
            r0[0] = acc[mt][nt][0] + b0;
            r1[0] = acc[mt][nt][1] + b1;
            r0[8] = acc[mt][nt][2] + b0;
            r1[8] = acc[mt][nt][3] + b1;
        }
    }
}

// ============================================================
// launch
// ============================================================
extern "C" void kernel_launch(void* const* d_in, const int* in_sizes, int n_in,
                              void* d_out, int out_size) {
    (void)in_sizes; (void)n_in; (void)out_size;
    const float* x      = (const float*)d_in[0];
    const float* weight = (const float*)d_in[1];
    const float* bias   = (const float*)d_in[2];
    const float* w_off  = (const float*)d_in[3];

    float* out = (float*)d_out;
    float* off = out + OUT_MAIN_ELEMS;   // second output: offsets [B,18,H,W]

    transpose_nchw_nhwc<<<dim3(WW / 32, CIN / 32, BB * HH), dim3(32, 8)>>>(x);
    transpose_weights<<<(K2 * CIN * COUT + 255) / 256, 256>>>(weight, w_off);
    offset_conv<<<dim3(WW / 16, HH / 16, BB), 256>>>(off);
    deform_mma<<<dim3(WW / 32, HH / 4, BB), 256>>>(bias, off, out);
}

// round 6
// speedup vs baseline: 2.4059x; 1.2788x over previous
#include <cuda_runtime.h>
#include <math.h>
#include <stdint.h>

#define BB   4
#define CIN  128
#define COUT 128
#define HH   96
#define WW   96
#define K2   9

#define OUT_MAIN_ELEMS (BB*COUT*HH*WW)   // 4718592
#define PLANE (HH*WW)                    // 9216

// ---- device scratch (no allocations allowed) ----
__device__ float g_xt[BB*HH*WW*CIN];        // x in NHWC
__device__ float g_mask[BB*K2*PLANE];       // sigmoid(om[18:27])*2
__device__ float g_wt2[K2*4*128*32];        // tf32 main weights: [tap*4+cq][oc128][c32]
__device__ float g_wofft2[K2*4*32*32];      // tf32 offset weights: [tap*4+cq][oc32][c32] (27 padded to 32)
__device__ float4 g_bw[BB*K2*PLANE];        // per (b,tap,px): 4 corner weights (mask*validity folded)
__device__ int4   g_bi[BB*K2*PLANE];        // per (b,tap,px): 4 corner base idx (float4 units)

__device__ __forceinline__ uint32_t f2tf32(float x) {
    uint32_t u;
    asm("cvt.rna.tf32.f32 %0, %1;" : "=r"(u) : "f"(x));
    return u;
}

__device__ __forceinline__ void mma_tf32(float d[4], const uint32_t a[4], const uint32_t b[2]) {
    asm volatile(
        "mma.sync.aligned.m16n8k8.row.col.f32.tf32.tf32.f32 "
        "{%0,%1,%2,%3}, {%4,%5,%6,%7}, {%8,%9}, {%0,%1,%2,%3};"
        : "+f"(d[0]), "+f"(d[1]), "+f"(d[2]), "+f"(d[3])
        : "r"(a[0]), "r"(a[1]), "r"(a[2]), "r"(a[3]), "r"(b[0]), "r"(b[1]));
}

// ============================================================
// 1) NCHW -> NHWC transpose of x
// ============================================================
__global__ void transpose_nchw_nhwc(const float* __restrict__ x) {
    __shared__ float t[32][33];
    int w0 = blockIdx.x * 32;
    int c0 = blockIdx.y * 32;
    int bh = blockIdx.z;
    int b = bh / HH;
    int h = bh % HH;
    const float* xb = x + (size_t)b * CIN * HH * WW;
#pragma unroll
    for (int i = 0; i < 32; i += 8) {
        int c = c0 + threadIdx.y + i;
        t[threadIdx.y + i][threadIdx.x] = xb[((size_t)c * HH + h) * WW + w0 + threadIdx.x];
    }
    __syncthreads();
    float* xt = g_xt + ((size_t)b * HH + h) * WW * CIN;
#pragma unroll
    for (int i = 0; i < 32; i += 8) {
        int w = w0 + threadIdx.y + i;
        xt[(size_t)w * CIN + c0 + threadIdx.x] = t[threadIdx.x][threadIdx.y + i];
    }
}

// ============================================================
// 2) Weight prep (both weight tensors -> tf32, chunked layouts)
// ============================================================
__global__ void transpose_weights(const float* __restrict__ weight,
                                  const float* __restrict__ w_off) {
    int idx = blockIdx.x * 256 + threadIdx.x;
    if (idx < K2 * CIN * COUT) {
        int tap = idx / (CIN * COUT);
        int r   = idx % (CIN * COUT);
        int c   = r >> 7;
        int oc  = r & 127;
        int blk = tap * 4 + (c >> 5);
        uint32_t tv = f2tf32(weight[((size_t)oc * CIN + c) * K2 + tap]);
        g_wt2[(size_t)blk * 4096 + oc * 32 + (c & 31)] = __uint_as_float(tv);
    }
    if (idx < K2 * 4 * 32 * 32) {   // 36864 as well
        int blk = idx >> 10;            // tap*4+cq
        int e   = idx & 1023;
        int oc  = e >> 5;
        int c32 = e & 31;
        int tap = blk >> 2, cq = blk & 3;
        int c = cq * 32 + c32;
        float v = (oc < 27) ? w_off[((size_t)oc * CIN + c) * K2 + tap] : 0.f;
        g_wofft2[idx] = __uint_as_float(f2tf32(v));
    }
}

// ============================================================
// 3) Offset/mask conv via tf32 MMA.
//    CTA: 256 px x 32 oc (27 used). 8 warps, warp tile 32px x 32oc.
//    K = 9 taps x 128 c in 36 chunks of 32.
// ============================================================
__global__ __launch_bounds__(256)
void offset_mma(float* __restrict__ out_off) {
    __shared__ uint32_t As[256 * 36];   // 36KB
    __shared__ uint32_t Bs[32 * 36];    // 4.6KB

    int tid = threadIdx.x;
    int wid = tid >> 5, lane = tid & 31;
    int g = lane >> 2, t = lane & 3;
    int pix0 = blockIdx.x * 256;
    int wpx0 = wid * 32;

    int gp = tid >> 3;          // pixel slot 0..31 within pass
    int gc = lane & 7;          // channel float4 slot

    float acc[2][4][4];
#pragma unroll
    for (int mt = 0; mt < 2; mt++)
#pragma unroll
        for (int nt = 0; nt < 4; nt++)
#pragma unroll
            for (int r = 0; r < 4; r++) acc[mt][nt][r] = 0.f;

    const float4* xt4 = (const float4*)g_xt;

    for (int chunk = 0; chunk < 36; ++chunk) {
        int tap = chunk >> 2, cq = chunk & 3;
        int ki = tap / 3, kj = tap % 3;
        __syncthreads();

        // stage Bs [32oc][32c]
        {
            const float4* bs = (const float4*)(g_wofft2 + (size_t)(tap * 4 + cq) * 1024);
            int oc = tid >> 3, c4 = (tid & 7) * 4;
            *(float4*)&Bs[oc * 36 + c4] = bs[tid];
        }

        // stage As: 8 passes of 32 px
#pragma unroll
        for (int pass = 0; pass < 8; pass++) {
            int p = pass * 32 + gp;
            int pixg = pix0 + p;
            int b = pixg / PLANE;
            int pr = pixg % PLANE;
            int h = pr / WW, w = pr % WW;
            int y = h + ki - 1, x = w + kj - 1;
            bool ok = (y >= 0) && (y < HH) && (x >= 0) && (x < WW);
            float4 v = make_float4(0.f, 0.f, 0.f, 0.f);
            if (ok) v = xt4[((size_t)b * PLANE + y * WW + x) * 32 + cq * 8 + gc];
            uint32_t* dst = &As[p * 36 + gc * 4];
            dst[0] = f2tf32(v.x);
            dst[1] = f2tf32(v.y);
            dst[2] = f2tf32(v.z);
            dst[3] = f2tf32(v.w);
        }
        __syncthreads();

        // mma
#pragma unroll
        for (int ks = 0; ks < 4; ks++) {
            int c0 = ks * 8 + t;
            uint32_t afrag[2][4];
#pragma unroll
            for (int mt = 0; mt < 2; mt++) {
                int row = wpx0 + mt * 16 + g;
                afrag[mt][0] = As[row * 36 + c0];
                afrag[mt][1] = As[(row + 8) * 36 + c0];
                afrag[mt][2] = As[row * 36 + c0 + 4];
                afrag[mt][3] = As[(row + 8) * 36 + c0 + 4];
            }
            uint32_t bfrag[4][2];
#pragma unroll
            for (int nt = 0; nt < 4; nt++) {
                int oc = nt * 8 + g;
                bfrag[nt][0] = Bs[oc * 36 + c0];
                bfrag[nt][1] = Bs[oc * 36 + c0 + 4];
            }
#pragma unroll
            for (int mt = 0; mt < 2; mt++)
#pragma unroll
                for (int nt = 0; nt < 4; nt++)
                    mma_tf32(acc[mt][nt], afrag[mt], bfrag[nt]);
        }
    }

    // epilogue: oc<18 -> offsets out; 18..26 -> mask; 27..31 dropped
#pragma unroll
    for (int nt = 0; nt < 4; nt++) {
        int oc0 = nt * 8 + 2 * t;
#pragma unroll
        for (int mt = 0; mt < 2; mt++) {
            int row = wpx0 + mt * 16 + g;
#pragma unroll
            for (int rr = 0; rr < 4; rr++) {
                int oc = oc0 + (rr & 1);
                int pixg = pix0 + row + (rr >> 1) * 8;
                float v = acc[mt][nt][rr];
                int b = pixg / PLANE;
                int pr = pixg % PLANE;
                if (oc < 18) {
                    out_off[((size_t)b * 18 + oc) * PLANE + pr] = v;
                } else if (oc < 27) {
                    g_mask[((size_t)b * 9 + (oc - 18)) * PLANE + pr] =
                        2.0f / (1.0f + expf(-v));
                }
            }
        }
    }
}

// ============================================================
// 4) Precompute bilinear params per (b, tap, px)
// ============================================================
__global__ void prep_bilinear(const float* __restrict__ off) {
    int idx = blockIdx.x * 256 + threadIdx.x;
    if (idx >= BB * K2 * PLANE) return;
    int b   = idx / (K2 * PLANE);
    int r   = idx % (K2 * PLANE);
    int tap = r / PLANE;
    int pix = r % PLANE;
    int h = pix / WW, w = pix % WW;

    float o1 = off[((size_t)b * 18 + tap) * PLANE + pix];
    float o2 = off[((size_t)b * 18 + 9 + tap) * PLANE + pix];
    float m  = g_mask[((size_t)b * 9 + tap) * PLANE + pix];

    int ki = tap / 3, kj = tap % 3;
    float py  = (float)(h - 1 + ki) + o1;
    float pxx = (float)(w - 1 + kj) + o2;
    float y0f = floorf(py), x0f = floorf(pxx);
    float ly = py - y0f, lx = pxx - x0f;
    float hy = 1.f - ly, hx = 1.f - lx;
    int y0 = (int)y0f, x0 = (int)x0f;
    int y1 = y0 + 1, x1 = x0 + 1;
    bool vy0 = (y0 >= 0) && (y0 < HH), vy1 = (y1 >= 0) && (y1 < HH);
    bool vx0 = (x0 >= 0) && (x0 < WW), vx1 = (x1 >= 0) && (x1 < WW);
    float4 wv;
    wv.x = (vy0 && vx0) ? hy * hx * m : 0.f;
    wv.y = (vy0 && vx1) ? hy * lx * m : 0.f;
    wv.z = (vy1 && vx0) ? ly * hx * m : 0.f;
    wv.w = (vy1 && vx1) ? ly * lx * m : 0.f;
    int y0c = min(max(y0, 0), HH - 1), y1c = min(max(y1, 0), HH - 1);
    int x0c = min(max(x0, 0), WW - 1), x1c = min(max(x1, 0), WW - 1);
    int4 iv;                         // float4-unit indices into this batch's xt
    iv.x = (y0c * WW + x0c) * 32;
    iv.y = (y0c * WW + x1c) * 32;
    iv.z = (y1c * WW + x0c) * 32;
    iv.w = (y1c * WW + x1c) * 32;
    g_bw[idx] = wv;
    g_bi[idx] = iv;
}

// ============================================================
// 5) Deformable conv: coalesced gather -> smem -> mma.sync tf32
//    CTA: M=128 px (4 ho x 32 wo) x N=128 oc; 36 K-chunks of 32 c.
//    8 warps; warp tile 32 px x 64 oc.
// ============================================================
__global__ __launch_bounds__(256)
void deform_mma(const float* __restrict__ bias,
                float* __restrict__ out) {
    __shared__ uint32_t As[128 * 36];
    __shared__ uint32_t Bs[128 * 36];

    int tid = threadIdx.x;
    int wid = tid >> 5, lane = tid & 31;
    int g = lane >> 2, t = lane & 3;
    int b   = blockIdx.z;
    int ho0 = blockIdx.y * 4;
    int wo0 = blockIdx.x * 32;

    int wpx0 = (wid & 3) * 32;
    int woc0 = (wid >> 2) * 64;

    int gp = tid >> 3;          // pixel slot 0..31 within pass
    int gc = lane & 7;          // channel float4 slot

    float acc[2][8][4];
#pragma unroll
    for (int mt = 0; mt < 2; mt++)
#pragma unroll
        for (int nt = 0; nt < 8; nt++)
#pragma unroll
            for (int r = 0; r < 4; r++) acc[mt][nt][r] = 0.f;

    const float4* xt4 = (const float4*)(g_xt + (size_t)b * PLANE * CIN);
    int pbase = (b * K2) * PLANE;

    for (int chunk = 0; chunk < 36; ++chunk) {
        int tap = chunk >> 2, cq = chunk & 3;
        __syncthreads();

        // stage weights [128 oc][32 c] -> Bs stride 36
        {
            const float4* wsrc = (const float4*)(g_wt2 + (size_t)(tap * 4 + cq) * 4096);
#pragma unroll
            for (int j = 0; j < 4; j++) {
                int idx4 = tid + j * 256;
                int oc = idx4 >> 3, c4 = (idx4 & 7) * 4;
                *(float4*)&Bs[oc * 36 + c4] = wsrc[idx4];
            }
        }

        // stage As: 4 passes of 32 px, fully coalesced corner reads
#pragma unroll
        for (int pass = 0; pass < 4; pass++) {
            int p = pass * 32 + gp;
            int pix = (ho0 + (p >> 5)) * WW + wo0 + (p & 31);
            int pa = pbase + tap * PLANE + pix;
            float4 wv = g_bw[pa];
            int4 iv   = g_bi[pa];
            int cc = cq * 8 + gc;
            float4 v00 = xt4[iv.x + cc];
            float4 v01 = xt4[iv.y + cc];
            float4 v10 = xt4[iv.z + cc];
            float4 v11 = xt4[iv.w + cc];
            uint32_t* dst = &As[p * 36 + gc * 4];
            dst[0] = f2tf32(wv.x * v00.x + wv.y * v01.x + wv.z * v10.x + wv.w * v11.x);
            dst[1] = f2tf32(wv.x * v00.y + wv.y * v01.y + wv.z * v10.y + wv.w * v11.y);
            dst[2] = f2tf32(wv.x * v00.z + wv.y * v01.z + wv.z * v10.z + wv.w * v11.z);
            dst[3] = f2tf32(wv.x * v00.w + wv.y * v01.w + wv.z * v10.w + wv.w * v11.w);
        }
        __syncthreads();

        // mma: 4 k-steps x (2 mt x 8 nt)
#pragma unroll
        for (int ks = 0; ks < 4; ks++) {
            int c0 = ks * 8 + t;
            uint32_t afrag[2][4];
#pragma unroll
            for (int mt = 0; mt < 2; mt++) {
                int row = wpx0 + mt * 16 + g;
                afrag[mt][0] = As[row * 36 + c0];
                afrag[mt][1] = As[(row + 8) * 36 + c0];
                afrag[mt][2] = As[row * 36 + c0 + 4];
                afrag[mt][3] = As[(row + 8) * 36 + c0 + 4];
            }
            uint32_t bfrag[8][2];
#pragma unroll
            for (int nt = 0; nt < 8; nt++) {
                int oc = woc0 + nt * 8 + g;
                bfrag[nt][0] = Bs[oc * 36 + c0];
                bfrag[nt][1] = Bs[oc * 36 + c0 + 4];
            }
#pragma unroll
            for (int mt = 0; mt < 2; mt++)
#pragma unroll
                for (int nt = 0; nt < 8; nt++)
                    mma_tf32(acc[mt][nt], afrag[mt], bfrag[nt]);
        }
    }

    // epilogue: acc -> out (NCHW) + bias
    int e_ho = ho0 + (wid & 3);
    float* ob = out + ((size_t)b * COUT) * PLANE + (size_t)e_ho * WW + wo0;
#pragma unroll
    for (int nt = 0; nt < 8; nt++) {
        int oc0 = woc0 + nt * 8 + 2 * t;
        float b0 = __ldg(&bias[oc0]);
        float b1 = __ldg(&bias[oc0 + 1]);
#pragma unroll
        for (int mt = 0; mt < 2; mt++) {
            int wo_a = mt * 16 + g;
            float* r0 = ob + (size_t)oc0 * PLANE + wo_a;
            float* r1 = ob + (size_t)(oc0 + 1) * PLANE + wo_a;
            r0[0] = acc[mt][nt][0] + b0;
            r1[0] = acc[mt][nt][1] + b1;
            r0[8] = acc[mt][nt][2] + b0;
            r1[8] = acc[mt][nt][3] + b1;
        }
    }
}

// ============================================================
// launch
// ============================================================
extern "C" void kernel_launch(void* const* d_in, const int* in_sizes, int n_in,
                              void* d_out, int out_size) {
    (void)in_sizes; (void)n_in; (void)out_size;
    const float* x      = (const float*)d_in[0];
    const float* weight = (const float*)d_in[1];
    const float* bias   = (const float*)d_in[2];
    const float* w_off  = (const float*)d_in[3];

    float* out = (float*)d_out;
    float* off = out + OUT_MAIN_ELEMS;   // second output: offsets [B,18,H,W]

    transpose_nchw_nhwc<<<dim3(WW / 32, CIN / 32, BB * HH), dim3(32, 8)>>>(x);
    transpose_weights<<<(K2 * CIN * COUT + 255) / 256, 256>>>(weight, w_off);
    offset_mma<<<(BB * PLANE) / 256, 256>>>(off);
    prep_bilinear<<<(BB * K2 * PLANE + 255) / 256, 256>>>(off);
    deform_mma<<<dim3(WW / 32, HH / 4, BB), 256>>>(bias, out);
}